// round 16
// baseline (speedup 1.0000x reference)
#include <cuda_runtime.h>
#include <cuda_bf16.h>
#include <cstdint>

// ---------------- problem constants ----------------
#define DD   12
#define HH   256
#define WW   256
#define HW_  (HH*WW)
#define DHW  (DD*HH*WW)
#define CEc  32
#define HID  256
#define NPATCH 1805      // 5*19*19
#define NPAD   1920      // 15 * 128
#define NP     10000     // 2*8*25*25 patches
#define BM   64
#define MT   157         // ceil(10000/64)
#define NT   15          // 1920/128
#define NCTA (MT * NT)   // 2355
#define PREP_BLOCKS 1920
#define PPB  25
#define MLP_BLOCKS (NP / PPB)   // 400

// ---------------- scratch (device globals, no allocs allowed) -----------
__device__ __nv_bfloat16 g_Hb[NP * HID];        // relu(emb@W1+b1), bf16 (compacted)
__device__ __nv_bfloat16 g_W2Tb[NPAD * HID];    // W2^T padded, bf16 [n][k]
__device__ int2     g_mmeta[NP];                // compacted {gb offset, cenpk}
__device__ int      g_noff[NPAD];               // per-n gt window offset, -1 pad
__device__ uint32_t g_wpk[2 * DHW];             // packed (min|max<<16) 2x2 window
__device__ double   g_acc[3];                   // num, sum(m*p*p), sum(m*t)
__device__ unsigned g_done;                     // completion counter
__device__ unsigned g_cnt;                      // compacted valid-patch count

// ======================= helpers ==========================
__device__ __forceinline__ uint32_t smem_u32(const void* p) {
    uint32_t a;
    asm("{ .reg .u64 t; cvta.to.shared.u64 t, %1; cvt.u32.u64 %0, t; }"
        : "=r"(a) : "l"(p));
    return a;
}
__device__ __forceinline__ float sigmoid_mufu(float z) {
    float u = -1.4426950408889634f * z;
    float ez; asm("ex2.approx.f32 %0, %1;" : "=f"(ez) : "f"(u));
    float d = 1.0f + ez;
    float r; asm("rcp.approx.f32 %0, %1;" : "=f"(r) : "f"(d));
    return r;
}
__device__ __forceinline__ uint32_t pack_mnmx(float a, float b, float c, float d) {
    int mn = (int)fminf(fminf(a, b), fminf(c, d));
    int mx = (int)fmaxf(fmaxf(a, b), fmaxf(c, d));
    return (uint32_t)mn | ((uint32_t)mx << 16);
}

// ===== fused pre-pass: prep blocks [0,1920) + mlp1 blocks [1920,2320) ====
#define PW_THREADS (2 * DHW / 4)   // 393216
__global__ __launch_bounds__(256)
void k_pre(const float* __restrict__ W2, const float* __restrict__ target,
           const float* __restrict__ pred, const float* __restrict__ W1,
           const float* __restrict__ b1) {
    __shared__ float W1s[CEc * HID];
    __shared__ float embs[PPB * CEc];
    __shared__ int   rowOf[PPB];
    int tid = threadIdx.x;

    if (blockIdx.x < PREP_BLOCKS) {
        // ---------------- prep part ----------------
        int idx = blockIdx.x * 256 + tid;

        // packed 2x2 window min/max over gt, 4 outputs per thread
        if (idx < PW_THREADS) {
            int i4 = idx * 4;
            int b = i4 / DHW; int r = i4 - b * DHW;
            int d = r / HW_;  int hw = r - d * HW_;
            int h = hw >> 8;  int w = hw & 255;          // w multiple of 4
            const float* g = target + (long)b * 4 * DHW + d * HW_ + hw;
            float4 v0 = *(const float4*)g;
            float  e0 = (w < 252) ? g[4] : v0.w;
            float4 v1; float e1;
            if (h < 255) {
                v1 = *(const float4*)(g + WW);
                e1 = (w < 252) ? g[WW + 4] : v1.w;
            } else { v1 = v0; e1 = e0; }
            uint4 out;
            out.x = pack_mnmx(v0.x, v0.y, v1.x, v1.y);
            out.y = pack_mnmx(v0.y, v0.z, v1.y, v1.z);
            out.z = pack_mnmx(v0.z, v0.w, v1.z, v1.w);
            out.w = pack_mnmx(v0.w, e0,   v1.w, e1);
            *(uint4*)&g_wpk[i4] = out;
        }

        if (idx < 3) g_acc[idx] = 0.0;
        if (idx == 3) g_done = 0u;
        if (idx < NPAD) {
            int n = idx;
            if (n < NPATCH) {
                int dp = n / 361, rr = n - dp * 361;
                int ii = rr / 19, jw = rr - ii * 19;
                g_noff[n] = dp * HW_ + 2 * ii * WW + 2 * jw;
            } else g_noff[n] = -1;
        }
        {
            int k = idx / NPAD;
            int n = idx - k * NPAD;
            float v = (n < NPATCH) ? W2[k * NPATCH + n] : 0.f;
            g_W2Tb[n * HID + k] = __float2bfloat16(v);
        }
        return;
    }

    // ---------------- mlp1 part (with compaction) ----------------
    int pbase = (blockIdx.x - PREP_BLOCKS) * PPB;

    for (int i = tid; i < CEc * HID; i += 256) W1s[i] = W1[i];

    for (int i = tid; i < PPB * CEc; i += 256) {
        int c = i / PPB, p = i - c * PPB;
        int n = pbase + p;
        int b = n / 5000;  int r = n - b * 5000;
        int pd = r / 625;  int r2 = r - pd * 625;
        int ph = r2 / 25;  int pw = r2 - ph * 25;
        int sp = ((2 + pd) * HH + (21 + 9 * ph)) * WW + (21 + 9 * pw);
        embs[p * CEc + c] = pred[(b * CEc + c) * DHW + sp];
    }

    int valid = 0, gb = 0, cpk = 0;
    if (tid < PPB) {
        int n = pbase + tid;
        int b = n / 5000;  int r = n - b * 5000;
        int pd = r / 625;  int r2 = r - pd * 625;
        int ph = r2 / 25;  int pw = r2 - ph * 25;
        int sp = ((2 + pd) * HH + (21 + 9 * ph)) * WW + (21 + 9 * pw);
        const float* tg = target + b * 4 * DHW;
        float c0 = tg[sp];
        float a1 = tg[1 * DHW + sp];
        float a2 = tg[2 * DHW + sp];
        float a3 = tg[3 * DHW + sp];
        valid = (c0 != 0.f && a1 == 1.f && a2 == 1.f && a3 == 1.f) ? 1 : 0;
        gb  = (b * DD + pd) * HW_ + (2 + 9 * ph) * WW + (2 + 9 * pw);
        cpk = (int)((uint32_t)(int)c0 * 0x10001u);
    }
    if (tid < 32) {
        unsigned msk = __ballot_sync(0xffffffffu, (tid < PPB) && valid);
        int base = 0;
        if (tid == 0 && msk) base = (int)atomicAdd(&g_cnt, (unsigned)__popc(msk));
        base = __shfl_sync(0xffffffffu, base, 0);
        if (tid < PPB)
            rowOf[tid] = valid ? base + __popc(msk & ((1u << tid) - 1)) : -1;
    }
    __syncthreads();
    if (tid < PPB && valid) {
        int2 meta; meta.x = gb; meta.y = cpk;
        g_mmeta[rowOf[tid]] = meta;
    }

    float bb = b1[tid];
    for (int p = 0; p < PPB; p++) {
        int row = rowOf[p];
        if (row < 0) continue;
        float acc = bb;
        const float* e = &embs[p * CEc];
#pragma unroll
        for (int c = 0; c < CEc; c++) acc = fmaf(e[c], W1s[c * HID + tid], acc);
        g_Hb[row * HID + tid] = __float2bfloat16(fmaxf(acc, 0.f));
    }
}

// ============ mma.sync bf16 GEMM (h @ W2) + fused epilogue + final ======
// CTA tile 64x128, 8 warps (warp tile 32x32), 4-stage cp.async, BK=32.
#define STG 4
#define A_BYTES 4096
#define B_BYTES 8192
#define STAGE_BYTES (A_BYTES + B_BYTES)        // 12288
#define META_OFF (STG * STAGE_BYTES)           // 49152
#define SMEM_DYN (META_OFF + 1024)             // 50176

__global__ __launch_bounds__(256, 4)
void k_gemm(const uint32_t* __restrict__ gwp, const float* __restrict__ b2,
            float* __restrict__ out) {
    extern __shared__ __align__(128) char sm[];
    int*   noffs = (int*)(sm + META_OFF);          // [128]
    float* b2s   = (float*)(sm + META_OFF + 512);  // [128]

    int tid = threadIdx.x;
    int wid = tid >> 5, lane = tid & 31;
    int n0 = blockIdx.x * 128;
    int m0 = blockIdx.y * BM;
    unsigned cnt = g_cnt;

    // inactive m-tile: participate in completion ticket, then leave
    if ((unsigned)m0 >= cnt) {
        if (tid == 0) {
            __threadfence();
            unsigned ticket = atomicAdd(&g_done, 1u);
            if (ticket == NCTA - 1) {
                double num = g_acc[0];
                double den = g_acc[1] + g_acc[2];
                if (den < 1e-6) den = 1e-6;
                out[0] = (float)(-2.0 * num / den);
            }
        }
        return;
    }

    if (tid < 128) {
        int n = n0 + tid;
        noffs[tid] = g_noff[n];
        b2s[tid]   = (n < NPATCH) ? __ldg(&b2[n]) : 0.f;
    }

    float c[2][4][4];
#pragma unroll
    for (int mi = 0; mi < 2; mi++)
#pragma unroll
        for (int ni = 0; ni < 4; ni++)
#pragma unroll
            for (int k = 0; k < 4; k++) c[mi][ni][k] = 0.f;

    int wm = (wid >> 2) * 32;
    int wn = (wid & 3) * 32;
    int jj = lane >> 3, rr = lane & 7;

    uint32_t sbase = smem_u32(sm);

    uint32_t aA[2][2], bA[2][2];
#pragma unroll
    for (int s = 0; s < 2; s++) {
#pragma unroll
        for (int mi = 0; mi < 2; mi++) {
            int mrow = wm + mi * 16 + (jj & 1) * 8 + rr;
            int ch = s * 2 + (jj >> 1);
            aA[s][mi] = sbase + mrow * 64 + ((ch ^ ((mrow >> 1) & 3)) * 16);
        }
#pragma unroll
        for (int nb = 0; nb < 2; nb++) {
            int nrow = wn + nb * 16 + (jj >> 1) * 8 + rr;
            int ch = s * 2 + (jj & 1);
            bA[s][nb] = sbase + A_BYTES + nrow * 64
                      + ((ch ^ ((nrow >> 1) & 3)) * 16);
        }
    }

    uint32_t stDstA, stDstB;
    const char* stSrcA;
    const char* stSrcB;
    int stSzA;
    {
        int r = tid >> 2, cch = tid & 3;
        uint32_t swz = (uint32_t)((cch ^ ((r >> 1) & 3)) * 16);
        stDstA = (uint32_t)(r * 64) + swz;
        stDstB = A_BYTES + stDstA;
        bool ok = (m0 + r < NP);
        stSrcA = ok ? (const char*)&g_Hb[(m0 + r) * HID + cch * 8]
                    : (const char*)&g_Hb[0];
        stSzA = ok ? 16 : 0;
        stSrcB = (const char*)&g_W2Tb[(n0 + r) * HID + cch * 8];
    }

    auto stage = [&](int it, int buf) {
        int koff = it * 64;
        uint32_t sb = sbase + buf * STAGE_BYTES;
        asm volatile("cp.async.cg.shared.global [%0], [%1], 16, %2;\n"
                     :: "r"(sb + stDstA), "l"(stSrcA + koff), "r"(stSzA));
        asm volatile("cp.async.cg.shared.global [%0], [%1], 16;\n"
                     :: "r"(sb + stDstB), "l"(stSrcB + koff));
        asm volatile("cp.async.cg.shared.global [%0], [%1], 16;\n"
                     :: "r"(sb + stDstB + 4096), "l"(stSrcB + 32768 + koff));
        asm volatile("cp.async.commit_group;\n" ::: "memory");
    };

    stage(0, 0);
    stage(1, 1);
    stage(2, 2);
    for (int it = 0; it < 8; it++) {
        if (it < 6)
            asm volatile("cp.async.wait_group 2;\n" ::: "memory");
        else if (it == 6)
            asm volatile("cp.async.wait_group 1;\n" ::: "memory");
        else
            asm volatile("cp.async.wait_group 0;\n" ::: "memory");
        __syncthreads();
        if (it + 3 < 8) stage(it + 3, (it + 3) & 3);

        uint32_t boff = (uint32_t)((it & 3) * STAGE_BYTES);
#pragma unroll
        for (int s = 0; s < 2; s++) {
            uint32_t a[2][4], b[2][4];
#pragma unroll
            for (int mi = 0; mi < 2; mi++)
                asm volatile(
                    "ldmatrix.sync.aligned.m8n8.x4.shared.b16 {%0,%1,%2,%3}, [%4];"
                    : "=r"(a[mi][0]), "=r"(a[mi][1]), "=r"(a[mi][2]), "=r"(a[mi][3])
                    : "r"(aA[s][mi] + boff));
#pragma unroll
            for (int nb = 0; nb < 2; nb++)
                asm volatile(
                    "ldmatrix.sync.aligned.m8n8.x4.shared.b16 {%0,%1,%2,%3}, [%4];"
                    : "=r"(b[nb][0]), "=r"(b[nb][1]), "=r"(b[nb][2]), "=r"(b[nb][3])
                    : "r"(bA[s][nb] + boff));
#pragma unroll
            for (int mi = 0; mi < 2; mi++)
#pragma unroll
                for (int ni = 0; ni < 4; ni++) {
                    uint32_t bb0 = b[ni >> 1][(ni & 1) * 2 + 0];
                    uint32_t bb1 = b[ni >> 1][(ni & 1) * 2 + 1];
                    asm volatile(
                        "mma.sync.aligned.m16n8k16.row.col.f32.bf16.bf16.f32 "
                        "{%0,%1,%2,%3},{%4,%5,%6,%7},{%8,%9},{%0,%1,%2,%3};"
                        : "+f"(c[mi][ni][0]), "+f"(c[mi][ni][1]),
                          "+f"(c[mi][ni][2]), "+f"(c[mi][ni][3])
                        : "r"(a[mi][0]), "r"(a[mi][1]), "r"(a[mi][2]), "r"(a[mi][3]),
                          "r"(bb0), "r"(bb1));
                }
        }
    }

    // ---- fused epilogue (compacted rows: all valid) ----
    float s_num = 0.f, s_dp = 0.f, s_dt = 0.f;
#pragma unroll
    for (int mi = 0; mi < 2; mi++)
#pragma unroll
        for (int h = 0; h < 2; h++) {
            int mloc = wm + mi * 16 + (lane >> 2) + h * 8;
            unsigned m = (unsigned)(m0 + mloc);
            if (m >= cnt) continue;
            int2 meta = __ldg(&g_mmeta[m]);
            uint32_t cenpk = (uint32_t)meta.y;
            const uint32_t* gw = gwp + meta.x;
#pragma unroll
            for (int ni = 0; ni < 4; ni++)
#pragma unroll
                for (int q = 0; q < 2; q++) {
                    int nloc = wn + ni * 8 + (lane & 3) * 2 + q;
                    int off = noffs[nloc];
                    if (off < 0) continue;
                    uint32_t w = __ldg(&gw[off]);
                    float tgt = (w != cenpk) ? 1.f : 0.f;
                    float msk = ((w & 0xFFFFu) == 0u) ? 0.f : 1.f;
                    float z = c[mi][ni][h * 2 + q] + b2s[nloc];
                    float p = sigmoid_mufu(z);
                    float pm = p * msk;
                    s_num = fmaf(pm, tgt, s_num);
                    s_dp  = fmaf(pm, p,  s_dp);
                    s_dt  = fmaf(msk, tgt, s_dt);
                }
        }

    // ---- reduce + atomics + fused final ----
#pragma unroll
    for (int o = 16; o; o >>= 1) {
        s_num += __shfl_xor_sync(0xffffffffu, s_num, o);
        s_dp  += __shfl_xor_sync(0xffffffffu, s_dp,  o);
        s_dt  += __shfl_xor_sync(0xffffffffu, s_dt,  o);
    }
    float* red = (float*)sm;
    __syncthreads();
    if (lane == 0) {
        red[wid * 3 + 0] = s_num;
        red[wid * 3 + 1] = s_dp;
        red[wid * 3 + 2] = s_dt;
    }
    __syncthreads();
    if (tid == 0) {
        float a0 = 0, a1 = 0, a2 = 0;
#pragma unroll
        for (int w = 0; w < 8; w++) {
            a0 += red[w * 3 + 0]; a1 += red[w * 3 + 1]; a2 += red[w * 3 + 2];
        }
        atomicAdd(&g_acc[0], (double)a0);
        atomicAdd(&g_acc[1], (double)a1);
        atomicAdd(&g_acc[2], (double)a2);
        __threadfence();
        unsigned ticket = atomicAdd(&g_done, 1u);
        if (ticket == NCTA - 1) {
            double num = g_acc[0];
            double den = g_acc[1] + g_acc[2];
            if (den < 1e-6) den = 1e-6;
            out[0] = (float)(-2.0 * num / den);
        }
    }
}

// ============================ launch ====================================
extern "C" void kernel_launch(void* const* d_in, const int* in_sizes, int n_in,
                              void* d_out, int out_size) {
    const float* target = (const float*)d_in[0];
    const float* pred   = (const float*)d_in[1];
    const float* W1     = (const float*)d_in[2];
    const float* b1     = (const float*)d_in[3];
    const float* W2     = (const float*)d_in[4];
    const float* b2     = (const float*)d_in[5];

    uint32_t* gwp;
    cudaGetSymbolAddress((void**)&gwp, g_wpk);
    unsigned* cntp;
    cudaGetSymbolAddress((void**)&cntp, g_cnt);

    static int init_done = 0;
    if (!init_done) {
        cudaFuncSetAttribute(k_gemm, cudaFuncAttributeMaxDynamicSharedMemorySize,
                             SMEM_DYN);
        init_done = 1;
    }

    cudaMemsetAsync(cntp, 0, sizeof(unsigned));
    k_pre<<<PREP_BLOCKS + MLP_BLOCKS, 256>>>(W2, target, pred, W1, b1);
    k_gemm<<<dim3(NT, MT), 256, SMEM_DYN>>>(gwp, b2, (float*)d_out);
}

// round 17
// speedup vs baseline: 1.0851x; 1.0851x over previous
#include <cuda_runtime.h>
#include <cuda_bf16.h>
#include <cstdint>

// ---------------- problem constants ----------------
#define DD   12
#define HH   256
#define WW   256
#define HW_  (HH*WW)
#define DHW  (DD*HH*WW)
#define CEc  32
#define HID  256
#define NPATCH 1805      // 5*19*19
#define NPAD   1920      // 15 * 128
#define NP     10000     // 2*8*25*25 patches
#define BM   64
#define MT   157         // ceil(10000/64)
#define NT   15          // 1920/128
#define NCTA (MT * NT)   // 2355
#define PPB  25
#define MLP_BLOCKS (NP / PPB)   // 400

// ---------------- scratch (device globals, no allocs allowed) -----------
__device__ __nv_bfloat16 g_Hb[NP * HID];        // relu(emb@W1+b1), bf16 (compacted)
__device__ __nv_bfloat16 g_W2Tb[NPAD * HID];    // W2^T padded, bf16 [n][k]
__device__ int2     g_mmeta[NP];                // compacted {gb offset, cenpk}
__device__ int      g_noff[NPAD];               // per-n gt window offset, -1 pad
__device__ uint32_t g_wpk[2 * DHW];             // packed (min|max<<16) 2x2 window
__device__ double   g_acc[3];                   // num, sum(m*p*p), sum(m*t)
__device__ unsigned g_done;                     // completion counter
__device__ unsigned g_cnt;                      // compacted valid-patch count

// ======================= helpers ==========================
__device__ __forceinline__ uint32_t smem_u32(const void* p) {
    uint32_t a;
    asm("{ .reg .u64 t; cvta.to.shared.u64 t, %1; cvt.u32.u64 %0, t; }"
        : "=r"(a) : "l"(p));
    return a;
}
__device__ __forceinline__ float sigmoid_mufu(float z) {
    float u = -1.4426950408889634f * z;
    float ez; asm("ex2.approx.f32 %0, %1;" : "=f"(ez) : "f"(u));
    float d = 1.0f + ez;
    float r; asm("rcp.approx.f32 %0, %1;" : "=f"(r) : "f"(d));
    return r;
}
__device__ __forceinline__ uint32_t pack_mnmx(float a, float b, float c, float d) {
    int mn = (int)fminf(fminf(a, b), fminf(c, d));
    int mx = (int)fmaxf(fmaxf(a, b), fmaxf(c, d));
    return (uint32_t)mn | ((uint32_t)mx << 16);
}

// ============== prep: W2^T, LUTs, counters + window field ===============
// grid: 1920 blocks x 256 = 491,520 threads. No smem -> high occupancy.
#define PW_THREADS (2 * DHW / 4)   // 393216
__global__ void k_prep_window(const float* __restrict__ W2,
                              const float* __restrict__ target) {
    int idx = blockIdx.x * 256 + threadIdx.x;

    // packed 2x2 window min/max over gt, 4 outputs per thread
    if (idx < PW_THREADS) {
        int i4 = idx * 4;
        int b = i4 / DHW; int r = i4 - b * DHW;
        int d = r / HW_;  int hw = r - d * HW_;
        int h = hw >> 8;  int w = hw & 255;          // w multiple of 4
        const float* g = target + (long)b * 4 * DHW + d * HW_ + hw;
        float4 v0 = *(const float4*)g;
        float  e0 = (w < 252) ? g[4] : v0.w;
        float4 v1; float e1;
        if (h < 255) {
            v1 = *(const float4*)(g + WW);
            e1 = (w < 252) ? g[WW + 4] : v1.w;
        } else { v1 = v0; e1 = e0; }
        uint4 out;
        out.x = pack_mnmx(v0.x, v0.y, v1.x, v1.y);
        out.y = pack_mnmx(v0.y, v0.z, v1.y, v1.z);
        out.z = pack_mnmx(v0.z, v0.w, v1.z, v1.w);
        out.w = pack_mnmx(v0.w, e0,   v1.w, e1);
        *(uint4*)&g_wpk[i4] = out;
    }

    if (idx < 3) g_acc[idx] = 0.0;
    if (idx == 3) g_done = 0u;
    if (idx == 4) g_cnt = 0u;           // reset before k_mlp1's atomics
    if (idx < NPAD) {
        int n = idx;
        if (n < NPATCH) {
            int dp = n / 361, rr = n - dp * 361;
            int ii = rr / 19, jw = rr - ii * 19;
            g_noff[n] = dp * HW_ + 2 * ii * WW + 2 * jw;
        } else g_noff[n] = -1;
    }
    {
        int k = idx / NPAD;
        int n = idx - k * NPAD;
        float v = (n < NPATCH) ? W2[k * NPATCH + n] : 0.f;
        g_W2Tb[n * HID + k] = __float2bfloat16(v);
    }
}

// ========== emb gather + MLP1 (bf16 out) with valid-compaction ==========
__global__ __launch_bounds__(256)
void k_mlp1(const float* __restrict__ target, const float* __restrict__ pred,
            const float* __restrict__ W1, const float* __restrict__ b1) {
    __shared__ float W1s[CEc * HID];
    __shared__ float embs[PPB * CEc];
    __shared__ int   rowOf[PPB];
    int tid = threadIdx.x;
    int pbase = blockIdx.x * PPB;

    for (int i = tid; i < CEc * HID; i += 256) W1s[i] = W1[i];

    for (int i = tid; i < PPB * CEc; i += 256) {
        int c = i / PPB, p = i - c * PPB;
        int n = pbase + p;
        int b = n / 5000;  int r = n - b * 5000;
        int pd = r / 625;  int r2 = r - pd * 625;
        int ph = r2 / 25;  int pw = r2 - ph * 25;
        int sp = ((2 + pd) * HH + (21 + 9 * ph)) * WW + (21 + 9 * pw);
        embs[p * CEc + c] = pred[(b * CEc + c) * DHW + sp];
    }

    int valid = 0, gb = 0, cpk = 0;
    if (tid < PPB) {
        int n = pbase + tid;
        int b = n / 5000;  int r = n - b * 5000;
        int pd = r / 625;  int r2 = r - pd * 625;
        int ph = r2 / 25;  int pw = r2 - ph * 25;
        int sp = ((2 + pd) * HH + (21 + 9 * ph)) * WW + (21 + 9 * pw);
        const float* tg = target + b * 4 * DHW;
        float c0 = tg[sp];
        float a1 = tg[1 * DHW + sp];
        float a2 = tg[2 * DHW + sp];
        float a3 = tg[3 * DHW + sp];
        valid = (c0 != 0.f && a1 == 1.f && a2 == 1.f && a3 == 1.f) ? 1 : 0;
        gb  = (b * DD + pd) * HW_ + (2 + 9 * ph) * WW + (2 + 9 * pw);
        cpk = (int)((uint32_t)(int)c0 * 0x10001u);
    }
    if (tid < 32) {
        unsigned msk = __ballot_sync(0xffffffffu, (tid < PPB) && valid);
        int base = 0;
        if (tid == 0 && msk) base = (int)atomicAdd(&g_cnt, (unsigned)__popc(msk));
        base = __shfl_sync(0xffffffffu, base, 0);
        if (tid < PPB)
            rowOf[tid] = valid ? base + __popc(msk & ((1u << tid) - 1)) : -1;
    }
    __syncthreads();
    if (tid < PPB && valid) {
        int2 meta; meta.x = gb; meta.y = cpk;
        g_mmeta[rowOf[tid]] = meta;
    }

    float bb = b1[tid];
    for (int p = 0; p < PPB; p++) {
        int row = rowOf[p];
        if (row < 0) continue;
        float acc = bb;
        const float* e = &embs[p * CEc];
#pragma unroll
        for (int c = 0; c < CEc; c++) acc = fmaf(e[c], W1s[c * HID + tid], acc);
        g_Hb[row * HID + tid] = __float2bfloat16(fmaxf(acc, 0.f));
    }
}

// ============ mma.sync bf16 GEMM (h @ W2) + fused epilogue + final ======
// CTA tile 64x128, 8 warps (warp tile 32x32), 4-stage cp.async, BK=32.
#define STG 4
#define A_BYTES 4096
#define B_BYTES 8192
#define STAGE_BYTES (A_BYTES + B_BYTES)        // 12288
#define META_OFF (STG * STAGE_BYTES)           // 49152
#define SMEM_DYN (META_OFF + 1024)             // 50176

__global__ __launch_bounds__(256, 4)
void k_gemm(const uint32_t* __restrict__ gwp, const float* __restrict__ b2,
            float* __restrict__ out) {
    extern __shared__ __align__(128) char sm[];
    int*   noffs = (int*)(sm + META_OFF);          // [128]
    float* b2s   = (float*)(sm + META_OFF + 512);  // [128]

    int tid = threadIdx.x;
    int wid = tid >> 5, lane = tid & 31;
    int n0 = blockIdx.x * 128;
    int m0 = blockIdx.y * BM;
    unsigned cnt = g_cnt;

    // inactive m-tile: participate in completion ticket, then leave
    if ((unsigned)m0 >= cnt) {
        if (tid == 0) {
            __threadfence();
            unsigned ticket = atomicAdd(&g_done, 1u);
            if (ticket == NCTA - 1) {
                double num = g_acc[0];
                double den = g_acc[1] + g_acc[2];
                if (den < 1e-6) den = 1e-6;
                out[0] = (float)(-2.0 * num / den);
            }
        }
        return;
    }

    if (tid < 128) {
        int n = n0 + tid;
        noffs[tid] = g_noff[n];
        b2s[tid]   = (n < NPATCH) ? __ldg(&b2[n]) : 0.f;
    }

    float c[2][4][4];
#pragma unroll
    for (int mi = 0; mi < 2; mi++)
#pragma unroll
        for (int ni = 0; ni < 4; ni++)
#pragma unroll
            for (int k = 0; k < 4; k++) c[mi][ni][k] = 0.f;

    int wm = (wid >> 2) * 32;
    int wn = (wid & 3) * 32;
    int jj = lane >> 3, rr = lane & 7;

    uint32_t sbase = smem_u32(sm);

    uint32_t aA[2][2], bA[2][2];
#pragma unroll
    for (int s = 0; s < 2; s++) {
#pragma unroll
        for (int mi = 0; mi < 2; mi++) {
            int mrow = wm + mi * 16 + (jj & 1) * 8 + rr;
            int ch = s * 2 + (jj >> 1);
            aA[s][mi] = sbase + mrow * 64 + ((ch ^ ((mrow >> 1) & 3)) * 16);
        }
#pragma unroll
        for (int nb = 0; nb < 2; nb++) {
            int nrow = wn + nb * 16 + (jj >> 1) * 8 + rr;
            int ch = s * 2 + (jj & 1);
            bA[s][nb] = sbase + A_BYTES + nrow * 64
                      + ((ch ^ ((nrow >> 1) & 3)) * 16);
        }
    }

    uint32_t stDstA, stDstB;
    const char* stSrcA;
    const char* stSrcB;
    int stSzA;
    {
        int r = tid >> 2, cch = tid & 3;
        uint32_t swz = (uint32_t)((cch ^ ((r >> 1) & 3)) * 16);
        stDstA = (uint32_t)(r * 64) + swz;
        stDstB = A_BYTES + stDstA;
        bool ok = (m0 + r < NP);
        stSrcA = ok ? (const char*)&g_Hb[(m0 + r) * HID + cch * 8]
                    : (const char*)&g_Hb[0];
        stSzA = ok ? 16 : 0;
        stSrcB = (const char*)&g_W2Tb[(n0 + r) * HID + cch * 8];
    }

    auto stage = [&](int it, int buf) {
        int koff = it * 64;
        uint32_t sb = sbase + buf * STAGE_BYTES;
        asm volatile("cp.async.cg.shared.global [%0], [%1], 16, %2;\n"
                     :: "r"(sb + stDstA), "l"(stSrcA + koff), "r"(stSzA));
        asm volatile("cp.async.cg.shared.global [%0], [%1], 16;\n"
                     :: "r"(sb + stDstB), "l"(stSrcB + koff));
        asm volatile("cp.async.cg.shared.global [%0], [%1], 16;\n"
                     :: "r"(sb + stDstB + 4096), "l"(stSrcB + 32768 + koff));
        asm volatile("cp.async.commit_group;\n" ::: "memory");
    };

    stage(0, 0);
    stage(1, 1);
    stage(2, 2);
    for (int it = 0; it < 8; it++) {
        if (it < 6)
            asm volatile("cp.async.wait_group 2;\n" ::: "memory");
        else if (it == 6)
            asm volatile("cp.async.wait_group 1;\n" ::: "memory");
        else
            asm volatile("cp.async.wait_group 0;\n" ::: "memory");
        __syncthreads();
        if (it + 3 < 8) stage(it + 3, (it + 3) & 3);

        uint32_t boff = (uint32_t)((it & 3) * STAGE_BYTES);
#pragma unroll
        for (int s = 0; s < 2; s++) {
            uint32_t a[2][4], b[2][4];
#pragma unroll
            for (int mi = 0; mi < 2; mi++)
                asm volatile(
                    "ldmatrix.sync.aligned.m8n8.x4.shared.b16 {%0,%1,%2,%3}, [%4];"
                    : "=r"(a[mi][0]), "=r"(a[mi][1]), "=r"(a[mi][2]), "=r"(a[mi][3])
                    : "r"(aA[s][mi] + boff));
#pragma unroll
            for (int nb = 0; nb < 2; nb++)
                asm volatile(
                    "ldmatrix.sync.aligned.m8n8.x4.shared.b16 {%0,%1,%2,%3}, [%4];"
                    : "=r"(b[nb][0]), "=r"(b[nb][1]), "=r"(b[nb][2]), "=r"(b[nb][3])
                    : "r"(bA[s][nb] + boff));
#pragma unroll
            for (int mi = 0; mi < 2; mi++)
#pragma unroll
                for (int ni = 0; ni < 4; ni++) {
                    uint32_t bb0 = b[ni >> 1][(ni & 1) * 2 + 0];
                    uint32_t bb1 = b[ni >> 1][(ni & 1) * 2 + 1];
                    asm volatile(
                        "mma.sync.aligned.m16n8k16.row.col.f32.bf16.bf16.f32 "
                        "{%0,%1,%2,%3},{%4,%5,%6,%7},{%8,%9},{%0,%1,%2,%3};"
                        : "+f"(c[mi][ni][0]), "+f"(c[mi][ni][1]),
                          "+f"(c[mi][ni][2]), "+f"(c[mi][ni][3])
                        : "r"(a[mi][0]), "r"(a[mi][1]), "r"(a[mi][2]), "r"(a[mi][3]),
                          "r"(bb0), "r"(bb1));
                }
        }
    }

    // ---- fused epilogue (compacted rows: all valid) ----
    float s_num = 0.f, s_dp = 0.f, s_dt = 0.f;
#pragma unroll
    for (int mi = 0; mi < 2; mi++)
#pragma unroll
        for (int h = 0; h < 2; h++) {
            int mloc = wm + mi * 16 + (lane >> 2) + h * 8;
            unsigned m = (unsigned)(m0 + mloc);
            if (m >= cnt) continue;
            int2 meta = __ldg(&g_mmeta[m]);
            uint32_t cenpk = (uint32_t)meta.y;
            const uint32_t* gw = gwp + meta.x;
#pragma unroll
            for (int ni = 0; ni < 4; ni++)
#pragma unroll
                for (int q = 0; q < 2; q++) {
                    int nloc = wn + ni * 8 + (lane & 3) * 2 + q;
                    int off = noffs[nloc];
                    if (off < 0) continue;
                    uint32_t w = __ldg(&gw[off]);
                    float tgt = (w != cenpk) ? 1.f : 0.f;
                    float msk = ((w & 0xFFFFu) == 0u) ? 0.f : 1.f;
                    float z = c[mi][ni][h * 2 + q] + b2s[nloc];
                    float p = sigmoid_mufu(z);
                    float pm = p * msk;
                    s_num = fmaf(pm, tgt, s_num);
                    s_dp  = fmaf(pm, p,  s_dp);
                    s_dt  = fmaf(msk, tgt, s_dt);
                }
        }

    // ---- reduce + atomics + fused final ----
#pragma unroll
    for (int o = 16; o; o >>= 1) {
        s_num += __shfl_xor_sync(0xffffffffu, s_num, o);
        s_dp  += __shfl_xor_sync(0xffffffffu, s_dp,  o);
        s_dt  += __shfl_xor_sync(0xffffffffu, s_dt,  o);
    }
    float* red = (float*)sm;
    __syncthreads();
    if (lane == 0) {
        red[wid * 3 + 0] = s_num;
        red[wid * 3 + 1] = s_dp;
        red[wid * 3 + 2] = s_dt;
    }
    __syncthreads();
    if (tid == 0) {
        float a0 = 0, a1 = 0, a2 = 0;
#pragma unroll
        for (int w = 0; w < 8; w++) {
            a0 += red[w * 3 + 0]; a1 += red[w * 3 + 1]; a2 += red[w * 3 + 2];
        }
        atomicAdd(&g_acc[0], (double)a0);
        atomicAdd(&g_acc[1], (double)a1);
        atomicAdd(&g_acc[2], (double)a2);
        __threadfence();
        unsigned ticket = atomicAdd(&g_done, 1u);
        if (ticket == NCTA - 1) {
            double num = g_acc[0];
            double den = g_acc[1] + g_acc[2];
            if (den < 1e-6) den = 1e-6;
            out[0] = (float)(-2.0 * num / den);
        }
    }
}

// ============================ launch ====================================
extern "C" void kernel_launch(void* const* d_in, const int* in_sizes, int n_in,
                              void* d_out, int out_size) {
    const float* target = (const float*)d_in[0];
    const float* pred   = (const float*)d_in[1];
    const float* W1     = (const float*)d_in[2];
    const float* b1     = (const float*)d_in[3];
    const float* W2     = (const float*)d_in[4];
    const float* b2     = (const float*)d_in[5];

    uint32_t* gwp;
    cudaGetSymbolAddress((void**)&gwp, g_wpk);

    static int init_done = 0;
    if (!init_done) {
        cudaFuncSetAttribute(k_gemm, cudaFuncAttributeMaxDynamicSharedMemorySize,
                             SMEM_DYN);
        init_done = 1;
    }

    k_prep_window<<<(HID * NPAD) / 256, 256>>>(W2, target);
    k_mlp1<<<MLP_BLOCKS, 256>>>(target, pred, W1, b1);
    k_gemm<<<dim3(NT, MT), 256, SMEM_DYN>>>(gwp, b2, (float*)d_out);
}